// round 3
// baseline (speedup 1.0000x reference)
#include <cuda_runtime.h>
#include <math.h>
#include <stdint.h>

#define O_DIM 1024
#define D_DIM 1024
#define E_NUM 16
#define TOPK  4
#define H_DIM 2048
#define A_DIM 64
#define NPAIR (O_DIM * TOPK)
#define FLT_MIN_NORM 1.17549435e-38f

// ---------------- scratch (static device memory; no allocs) ----------------
__device__ int   g_topk_idx[NPAIR];
__device__ float g_topk_gate[NPAIR];
__device__ float g_importance[O_DIM];
__device__ float g_load[O_DIM];
__device__ int   g_base[E_NUM + 1];
__device__ int   g_rows_sorted[NPAIR];
__device__ int   g_pair_of[NPAIR];
__device__ float g_h[NPAIR * H_DIM];   // 32 MB relu(fc1) activations
__device__ float g_z[NPAIR * A_DIM];   // 1 MB  fc2 outputs per pair

// ---------------- helpers ----------------
__device__ __forceinline__ unsigned f2tf(float x) {
    unsigned u;
    asm("cvt.rna.tf32.f32 %0, %1;" : "=r"(u) : "f"(x));
    return u;
}

__device__ __forceinline__ void mma_tf32(float c[4], unsigned a0, unsigned a1,
                                         unsigned a2, unsigned a3,
                                         unsigned b0, unsigned b1) {
    asm volatile(
        "mma.sync.aligned.m16n8k8.row.col.f32.tf32.tf32.f32 "
        "{%0,%1,%2,%3}, {%4,%5,%6,%7}, {%8,%9}, {%0,%1,%2,%3};\n"
        : "+f"(c[0]), "+f"(c[1]), "+f"(c[2]), "+f"(c[3])
        : "r"(a0), "r"(a1), "r"(a2), "r"(a3), "r"(b0), "r"(b1));
}

// ---------------- K1: gating (logits, top-4, softmax, importance/load) -----
__global__ __launch_bounds__(256) void gate_kernel(const float* __restrict__ obs,
                                                   const float* __restrict__ wg) {
    int o = blockIdx.x;
    int tid = threadIdx.x;
    const float* wrow = wg + (size_t)o * D_DIM * E_NUM;
    const float* orow = obs + (size_t)o * D_DIM;

    float acc[E_NUM];
#pragma unroll
    for (int i = 0; i < E_NUM; i++) acc[i] = 0.f;

    for (int d = tid; d < D_DIM; d += 256) {
        float x = orow[d];
        const float4* p = reinterpret_cast<const float4*>(wrow + (size_t)d * E_NUM);
        float4 v0 = p[0], v1 = p[1], v2 = p[2], v3 = p[3];
        acc[0]  += x * v0.x; acc[1]  += x * v0.y; acc[2]  += x * v0.z; acc[3]  += x * v0.w;
        acc[4]  += x * v1.x; acc[5]  += x * v1.y; acc[6]  += x * v1.z; acc[7]  += x * v1.w;
        acc[8]  += x * v2.x; acc[9]  += x * v2.y; acc[10] += x * v2.z; acc[11] += x * v2.w;
        acc[12] += x * v3.x; acc[13] += x * v3.y; acc[14] += x * v3.z; acc[15] += x * v3.w;
    }
#pragma unroll
    for (int i = 0; i < E_NUM; i++) {
#pragma unroll
        for (int off = 16; off; off >>= 1)
            acc[i] += __shfl_xor_sync(0xffffffffu, acc[i], off);
    }
    __shared__ float s[8][E_NUM];
    int warp = tid >> 5, lane = tid & 31;
    if (lane == 0) {
#pragma unroll
        for (int i = 0; i < E_NUM; i++) s[warp][i] = acc[i];
    }
    __syncthreads();
    if (tid == 0) {
        float logit[E_NUM];
        for (int e = 0; e < E_NUM; e++) {
            float t = 0.f;
            for (int w = 0; w < 8; w++) t += s[w][e];
            logit[e] = t;
        }
        bool taken[E_NUM];
        for (int e = 0; e < E_NUM; e++) taken[e] = false;
        int idx[TOPK]; float val[TOPK];
        for (int k = 0; k < TOPK; k++) {
            float best = -3.4e38f; int bi = 0;
            for (int e = 0; e < E_NUM; e++)
                if (!taken[e] && logit[e] > best) { best = logit[e]; bi = e; }
            taken[bi] = true; idx[k] = bi; val[k] = best;
        }
        float m = val[0];   // first pick is the max
        float ex[TOPK]; float se = 0.f;
        for (int k = 0; k < TOPK; k++) { ex[k] = expf(val[k] - m); se += ex[k]; }
        float gates[E_NUM];
        for (int e = 0; e < E_NUM; e++) gates[e] = 0.f;
        for (int k = 0; k < TOPK; k++) gates[idx[k]] = ex[k] / se;
        float imp = 0.f; int ldc = 0;
        for (int e = 0; e < E_NUM; e++) { imp += gates[e]; ldc += (gates[e] > 0.f); }
        for (int k = 0; k < TOPK; k++) {
            g_topk_idx[o * TOPK + k]  = idx[k];
            g_topk_gate[o * TOPK + k] = gates[idx[k]];
        }
        g_importance[o] = imp;
        g_load[o] = (float)ldc;
    }
}

// ---------------- K2: deterministic binning (warp-per-expert) --------------
__global__ __launch_bounds__(512) void bin_kernel() {
    int tid = threadIdx.x;
    int warp = tid >> 5, lane = tid & 31;
    int e = warp;  // 16 warps, one per expert
    __shared__ int scnt[E_NUM];
    __shared__ int sbase[E_NUM + 1];

    // pass 1: count
    int cnt = 0;
    for (int base = 0; base < O_DIM; base += 32) {
        int r = base + lane;
        int i0 = g_topk_idx[r * 4 + 0];
        int i1 = g_topk_idx[r * 4 + 1];
        int i2 = g_topk_idx[r * 4 + 2];
        int i3 = g_topk_idx[r * 4 + 3];
        bool f = (i0 == e) || (i1 == e) || (i2 == e) || (i3 == e);
        unsigned m = __ballot_sync(0xffffffffu, f);
        cnt += __popc(m);
    }
    if (lane == 0) scnt[e] = cnt;
    __syncthreads();
    if (tid == 0) {
        int s = 0;
        for (int q = 0; q < E_NUM; q++) { sbase[q] = s; s += scnt[q]; }
        sbase[E_NUM] = s;
    }
    __syncthreads();
    if (tid < E_NUM + 1) g_base[tid] = sbase[tid];

    // pass 2: compact
    int off = sbase[e];
    for (int base = 0; base < O_DIM; base += 32) {
        int r = base + lane;
        int j = -1;
        if      (g_topk_idx[r * 4 + 0] == e) j = 0;
        else if (g_topk_idx[r * 4 + 1] == e) j = 1;
        else if (g_topk_idx[r * 4 + 2] == e) j = 2;
        else if (g_topk_idx[r * 4 + 3] == e) j = 3;
        bool f = (j >= 0);
        unsigned m = __ballot_sync(0xffffffffu, f);
        int pos = off + __popc(m & ((1u << lane) - 1u));
        if (f) {
            g_rows_sorted[pos] = r;
            g_pair_of[r * 4 + j] = pos;
        }
        off += __popc(m);
    }
}

// ---------------- K3: loss (two-pass variance, ddof=1) ---------------------
__global__ __launch_bounds__(1024) void loss_kernel(float* __restrict__ out) {
    int tid = threadIdx.x;
    __shared__ float sh[32];
    __shared__ float bc;
    float imp = g_importance[tid];
    float ld  = g_load[tid];

    auto reduceSum = [&](float v) -> float {
#pragma unroll
        for (int o2 = 16; o2; o2 >>= 1) v += __shfl_xor_sync(0xffffffffu, v, o2);
        if ((tid & 31) == 0) sh[tid >> 5] = v;
        __syncthreads();
        if (tid < 32) {
            float r = sh[tid];
#pragma unroll
            for (int o2 = 16; o2; o2 >>= 1) r += __shfl_xor_sync(0xffffffffu, r, o2);
            if (tid == 0) bc = r;
        }
        __syncthreads();
        float r = bc;
        __syncthreads();
        return r;
    };

    float si  = reduceSum(imp);
    float mi  = si / (float)O_DIM;
    float di  = imp - mi;
    float ssi = reduceSum(di * di);
    float sl  = reduceSum(ld);
    float ml  = sl / (float)O_DIM;
    float dl  = ld - ml;
    float ssl = reduceSum(dl * dl);
    if (tid == 0) {
        float vi = ssi / (float)(O_DIM - 1);
        float vl = ssl / (float)(O_DIM - 1);
        float loss = (vi / (mi * mi + 1e-10f) + vl / (ml * ml + 1e-10f)) * 0.01f;
        out[3 * O_DIM * A_DIM] = loss;
    }
}

// ---------------- K4: action head (mu, softmax, log) -----------------------
// Reference runs with FTZ/DAZ (XLA:CPU): exp() results below FLT_MIN flush to
// 0, and the division p = ef/ssum ALSO flushes denormal results to 0. Where
// p == 0 the reference adds z = 1e-8, giving log(1e-8) = -18.4207 exactly.
// We emulate the flushes explicitly (GPU default keeps denormals).
__global__ __launch_bounds__(512) void action_kernel(const float* __restrict__ obs,
                                                     const float* __restrict__ lastw,
                                                     const float* __restrict__ lastb,
                                                     float* __restrict__ out) {
    int o = blockIdx.x;
    int tid = threadIdx.x;
    int a = tid & 63, chunk = tid >> 6;  // 8 chunks x 128 d each

    __shared__ float obsS[D_DIM];
    obsS[tid]       = obs[(size_t)o * D_DIM + tid];
    obsS[tid + 512] = obs[(size_t)o * D_DIM + tid + 512];
    __syncthreads();

    const float* lw = lastw + (size_t)o * D_DIM * A_DIM + (size_t)chunk * 128 * A_DIM + a;
    float acc = 0.f;
#pragma unroll 8
    for (int d = 0; d < 128; d++)
        acc += obsS[chunk * 128 + d] * lw[(size_t)d * A_DIM];

    __shared__ float red[8][A_DIM];
    red[chunk][a] = acc;
    __syncthreads();

    __shared__ float muS[A_DIM];
    __shared__ float eS[A_DIM];
    if (tid < A_DIM) {
        float m = 0.f;
        for (int c = 0; c < 8; c++) m += red[c][tid];
        muS[tid] = m + lastb[o * A_DIM + tid];
    }
    __syncthreads();
    if (tid < A_DIM) {
        float mx = muS[0];
        for (int i = 1; i < A_DIM; i++) mx = fmaxf(mx, muS[i]);
        float t  = muS[tid] - mx;
        float ef = expf(t);
        if (ef < FLT_MIN_NORM) ef = 0.f;          // FTZ: flush denormal exp result
        eS[tid] = ef;
    }
    __syncthreads();
    if (tid < A_DIM) {
        float ssum = 0.f;
        for (int i = 0; i < A_DIM; i++) ssum += eS[i];
        float p = eS[tid] / ssum;
        if (p < FLT_MIN_NORM) p = 0.f;            // FTZ: flush denormal quotient
        out[(size_t)o * A_DIM + tid] = p;
        float lp = (p == 0.f) ? logf(1e-8f) : logf(p);
        out[(size_t)O_DIM * A_DIM + o * A_DIM + tid] = lp;
    }
}

// ---------------- K5: grouped GEMM fc1 (gathered rows @ w1[e], relu) -------
// block tile: 64(M) x 128(N), K-chunk 32; 8 warps (2x4), warp tile 32x32
__global__ __launch_bounds__(256) void expert_fc1_kernel(const float* __restrict__ obs,
                                                         const float* __restrict__ w1,
                                                         const float* __restrict__ b1) {
    int e = blockIdx.z, mt = blockIdx.y, nt = blockIdx.x;
    int pb = g_base[e];
    int ne = g_base[e + 1] - pb;
    int m0 = mt * 64;
    if (m0 >= ne) return;

    __shared__ unsigned As[64][40];
    __shared__ unsigned Bs[32][136];
    __shared__ int rowid[64];

    int tid = threadIdx.x;
    int lane = tid & 31, warp = tid >> 5;
    int wm = warp >> 2, wn = warp & 3;

    if (tid < 64) {
        int mi = m0 + tid;
        rowid[tid] = g_rows_sorted[pb + (mi < ne ? mi : 0)];
    }
    float c[2][4][4];
#pragma unroll
    for (int i = 0; i < 2; i++)
#pragma unroll
        for (int j = 0; j < 4; j++)
#pragma unroll
            for (int q = 0; q < 4; q++) c[i][j][q] = 0.f;

    const float* w1e = w1 + (size_t)e * D_DIM * H_DIM + (size_t)nt * 128;
    __syncthreads();

    for (int kb = 0; kb < D_DIM; kb += 32) {
        // A tile: 64 x 32 gathered obs rows
#pragma unroll
        for (int i = 0; i < 2; i++) {
            int v = tid + i * 256;
            int r = v >> 3, seg = v & 7;
            const float4* src = reinterpret_cast<const float4*>(
                obs + (size_t)rowid[r] * D_DIM + kb + seg * 4);
            float4 f = *src;
            As[r][seg * 4 + 0] = f2tf(f.x);
            As[r][seg * 4 + 1] = f2tf(f.y);
            As[r][seg * 4 + 2] = f2tf(f.z);
            As[r][seg * 4 + 3] = f2tf(f.w);
        }
        // B tile: 32 x 128 of w1[e]
#pragma unroll
        for (int i = 0; i < 4; i++) {
            int v = tid + i * 256;
            int k = v >> 5, seg = v & 31;
            const float4* src = reinterpret_cast<const float4*>(
                w1e + (size_t)(kb + k) * H_DIM + seg * 4);
            float4 f = *src;
            Bs[k][seg * 4 + 0] = f2tf(f.x);
            Bs[k][seg * 4 + 1] = f2tf(f.y);
            Bs[k][seg * 4 + 2] = f2tf(f.z);
            Bs[k][seg * 4 + 3] = f2tf(f.w);
        }
        __syncthreads();
#pragma unroll
        for (int ks = 0; ks < 4; ks++) {
            int k8 = ks * 8;
            unsigned af[2][4], bf[4][2];
#pragma unroll
            for (int i = 0; i < 2; i++) {
                int r0 = wm * 32 + i * 16 + (lane >> 2);
                int kk = k8 + (lane & 3);
                af[i][0] = As[r0][kk];
                af[i][1] = As[r0 + 8][kk];
                af[i][2] = As[r0][kk + 4];
                af[i][3] = As[r0 + 8][kk + 4];
            }
#pragma unroll
            for (int j = 0; j < 4; j++) {
                int col = wn * 32 + j * 8 + (lane >> 2);
                bf[j][0] = Bs[k8 + (lane & 3)][col];
                bf[j][1] = Bs[k8 + (lane & 3) + 4][col];
            }
#pragma unroll
            for (int i = 0; i < 2; i++)
#pragma unroll
                for (int j = 0; j < 4; j++)
                    mma_tf32(c[i][j], af[i][0], af[i][1], af[i][2], af[i][3],
                             bf[j][0], bf[j][1]);
        }
        __syncthreads();
    }

    const float* b1e = b1 + e * H_DIM + nt * 128;
#pragma unroll
    for (int i = 0; i < 2; i++) {
        int r0 = m0 + wm * 32 + i * 16 + (lane >> 2);
#pragma unroll
        for (int j = 0; j < 4; j++) {
            int c0 = wn * 32 + j * 8 + 2 * (lane & 3);
            float bv0 = b1e[c0], bv1 = b1e[c0 + 1];
            if (r0 < ne) {
                float* dst = g_h + (size_t)(pb + r0) * H_DIM + nt * 128 + c0;
                dst[0] = fmaxf(c[i][j][0] + bv0, 0.f);
                dst[1] = fmaxf(c[i][j][1] + bv1, 0.f);
            }
            if (r0 + 8 < ne) {
                float* dst = g_h + (size_t)(pb + r0 + 8) * H_DIM + nt * 128 + c0;
                dst[0] = fmaxf(c[i][j][2] + bv0, 0.f);
                dst[1] = fmaxf(c[i][j][3] + bv1, 0.f);
            }
        }
    }
}

// ---------------- K6: grouped GEMM fc2 (h @ w2[e]) --------------------------
// block tile: 64(M) x 64(N), K-chunk 32; 8 warps (2x4), warp tile 32x16
__global__ __launch_bounds__(256) void expert_fc2_kernel(const float* __restrict__ w2) {
    int e = blockIdx.z, mt = blockIdx.y;
    int pb = g_base[e];
    int ne = g_base[e + 1] - pb;
    int m0 = mt * 64;
    if (m0 >= ne) return;

    __shared__ unsigned As[64][40];
    __shared__ unsigned Bs[32][72];

    int tid = threadIdx.x;
    int lane = tid & 31, warp = tid >> 5;
    int wm = warp >> 2, wn = warp & 3;

    float c[2][2][4];
#pragma unroll
    for (int i = 0; i < 2; i++)
#pragma unroll
        for (int j = 0; j < 2; j++)
#pragma unroll
            for (int q = 0; q < 4; q++) c[i][j][q] = 0.f;

    const float* w2e = w2 + (size_t)e * H_DIM * A_DIM;

    for (int kb = 0; kb < H_DIM; kb += 32) {
        // A tile: 64 x 32 of grouped h rows (contiguous)
#pragma unroll
        for (int i = 0; i < 2; i++) {
            int v = tid + i * 256;
            int r = v >> 3, seg = v & 7;
            int row = pb + m0 + r;
            if (row > NPAIR - 1) row = NPAIR - 1;   // clamp OOB (masked on store)
            const float4* src = reinterpret_cast<const float4*>(
                g_h + (size_t)row * H_DIM + kb + seg * 4);
            float4 f = *src;
            As[r][seg * 4 + 0] = f2tf(f.x);
            As[r][seg * 4 + 1] = f2tf(f.y);
            As[r][seg * 4 + 2] = f2tf(f.z);
            As[r][seg * 4 + 3] = f2tf(f.w);
        }
        // B tile: 32 x 64 of w2[e]
#pragma unroll
        for (int i = 0; i < 2; i++) {
            int v = tid + i * 256;
            int k = v >> 4, seg = v & 15;
            const float4* src = reinterpret_cast<const float4*>(
                w2e + (size_t)(kb + k) * A_DIM + seg * 4);
            float4 f = *src;
            Bs[k][seg * 4 + 0] = f2tf(f.x);
            Bs[k][seg * 4 + 1] = f2tf(f.y);
            Bs[k][seg * 4 + 2] = f2tf(f.z);
            Bs[k][seg * 4 + 3] = f2tf(f.w);
        }
        __syncthreads();
#pragma unroll
        for (int ks = 0; ks < 4; ks++) {
            int k8 = ks * 8;
            unsigned af[2][4], bf[2][2];
#pragma unroll
            for (int i = 0; i < 2; i++) {
                int r0 = wm * 32 + i * 16 + (lane >> 2);
                int kk = k8 + (lane & 3);
                af[i][0] = As[r0][kk];
                af[i][1] = As[r0 + 8][kk];
                af[i][2] = As[r0][kk + 4];
                af[i][3] = As[r0 + 8][kk + 4];
            }
#pragma unroll
            for (int j = 0; j < 2; j++) {
                int col = wn * 16 + j * 8 + (lane >> 2);
                bf[j][0] = Bs[k8 + (lane & 3)][col];
                bf[j][1] = Bs[k8 + (lane & 3) + 4][col];
            }
#pragma unroll
            for (int i = 0; i < 2; i++)
#pragma unroll
                for (int j = 0; j < 2; j++)
                    mma_tf32(c[i][j], af[i][0], af[i][1], af[i][2], af[i][3],
                             bf[j][0], bf[j][1]);
        }
        __syncthreads();
    }

#pragma unroll
    for (int i = 0; i < 2; i++) {
        int r0 = m0 + wm * 32 + i * 16 + (lane >> 2);
#pragma unroll
        for (int j = 0; j < 2; j++) {
            int c0 = wn * 16 + j * 8 + 2 * (lane & 3);
            if (r0 < ne) {
                float* dst = g_z + (size_t)(pb + r0) * A_DIM + c0;
                dst[0] = c[i][j][0];
                dst[1] = c[i][j][1];
            }
            if (r0 + 8 < ne) {
                float* dst = g_z + (size_t)(pb + r0 + 8) * A_DIM + c0;
                dst[0] = c[i][j][2];
                dst[1] = c[i][j][3];
            }
        }
    }
}

// ---------------- K7: combine y = sum_j gate * (z + b2[e]) ------------------
__global__ __launch_bounds__(256) void combine_kernel(const float* __restrict__ b2,
                                                      float* __restrict__ out) {
    int i = blockIdx.x * blockDim.x + threadIdx.x;
    if (i >= O_DIM * A_DIM) return;
    int o = i >> 6, a = i & 63;
    float y = 0.f;
#pragma unroll
    for (int j = 0; j < TOPK; j++) {
        int eidx = g_topk_idx[o * TOPK + j];
        float g  = g_topk_gate[o * TOPK + j];
        int p    = g_pair_of[o * TOPK + j];
        y += g * (g_z[(size_t)p * A_DIM + a] + b2[eidx * A_DIM + a]);
    }
    out[2 * O_DIM * A_DIM + i] = y;
}

// ---------------- launch ----------------------------------------------------
extern "C" void kernel_launch(void* const* d_in, const int* in_sizes, int n_in,
                              void* d_out, int out_size) {
    const float* obs   = (const float*)d_in[0];
    const float* wgate = (const float*)d_in[1];
    const float* w1    = (const float*)d_in[2];
    const float* b1    = (const float*)d_in[3];
    const float* w2    = (const float*)d_in[4];
    const float* b2    = (const float*)d_in[5];
    const float* lastw = (const float*)d_in[6];
    const float* lastb = (const float*)d_in[7];
    float* out = (float*)d_out;

    gate_kernel<<<O_DIM, 256>>>(obs, wgate);
    bin_kernel<<<1, 512>>>();
    loss_kernel<<<1, 1024>>>(out);
    action_kernel<<<O_DIM, 512>>>(obs, lastw, lastb, out);
    expert_fc1_kernel<<<dim3(16, 16, 16), 256>>>(obs, w1, b1);
    expert_fc2_kernel<<<dim3(1, 16, 16), 256>>>(w2);
    combine_kernel<<<(O_DIM * A_DIM + 255) / 256, 256>>>(b2, out);
}